// round 6
// baseline (speedup 1.0000x reference)
#include <cuda_runtime.h>
#include <cuda_bf16.h>
#include <cstdint>

// ArcFace loss, fused. HMMA GEMM (tcgen05 unavailable: harness targets compute_103 base).
// B=512, D=512, C=64000.
constexpr int BB = 512;
constexpr int DD = 512;
constexpr int CC = 64000;

constexpr int BM = 128, BN = 128, BK = 32;
constexpr int MT = BB / BM;    // 4
constexpr int NT = CC / BN;    // 500
constexpr int NSTG = DD / BK;  // 16
constexpr int AROW = 40;       // smem row stride (halfs); ldsm conflict-free
constexpr int A_STG = BM * AROW * 2;   // 10240 B
constexpr int B_STG = BN * AROW * 2;   // 10240 B
constexpr int NPIPE = 4;

// dynamic smem layout
constexpr int A_OFF  = 0;                      // 4 stages
constexpr int B_OFF  = NPIPE * A_STG;          // 40960, 4 stages
constexpr int SY_OFF = B_OFF + NPIPE * B_STG;  // 81920: 128 ints
constexpr int RA_OFF = SY_OFF + 512;           // 82432: 128x4 floats
constexpr int SMEM_TOTAL = RA_OFF + 2048;      // 84480 (x2 CTA = 169KB <= 228KB)

__device__ float         g_xn[BB * DD];    // normalized x fp32 (k3 exact dot)
__device__ __nv_bfloat16 g_xnb[BB * DD];   // normalized x bf16 (GEMM A)
__device__ __nv_bfloat16 g_wnb[CC * DD];   // normalized W bf16 (GEMM B)
__device__ int           g_y[BB];
__device__ float         g_partial[MT * NT * BM];
__device__ double        g_term[BB];

// ---------------- PTX helpers ----------------
__device__ __forceinline__ void ldsm4(uint32_t* r, uint32_t a) {
    asm volatile("ldmatrix.sync.aligned.m8n8.x4.shared.b16 {%0,%1,%2,%3}, [%4];"
        : "=r"(r[0]), "=r"(r[1]), "=r"(r[2]), "=r"(r[3]) : "r"(a));
}
__device__ __forceinline__ void mma16816(float* c, const uint32_t* a, uint32_t b0, uint32_t b1) {
    asm volatile("mma.sync.aligned.m16n8k16.row.col.f32.bf16.bf16.f32 "
        "{%0,%1,%2,%3}, {%4,%5,%6,%7}, {%8,%9}, {%0,%1,%2,%3};"
        : "+f"(c[0]), "+f"(c[1]), "+f"(c[2]), "+f"(c[3])
        : "r"(a[0]), "r"(a[1]), "r"(a[2]), "r"(a[3]), "r"(b0), "r"(b1));
}
__device__ __forceinline__ void cpasync16(uint32_t smem, const void* gptr) {
    asm volatile("cp.async.cg.shared.global [%0], [%1], 16;"
        :: "r"(smem), "l"(gptr) : "memory");
}
__device__ __forceinline__ void cpcommit() { asm volatile("cp.async.commit_group;" ::: "memory"); }
__device__ __forceinline__ void cpwait2() { asm volatile("cp.async.wait_group 2;" ::: "memory"); }

// ---------------------------------------------------------------------------
__global__ void k0_decode_y(const int* __restrict__ yw) {
    __shared__ int oddnz;
    int t = threadIdx.x;
    if (t == 0) oddnz = 0;
    __syncthreads();
    if (t < 256 && yw[2 * t + 1] != 0) atomicOr(&oddnz, 1);
    __syncthreads();
    if (oddnz == 0) g_y[t] = (int)((const long long*)yw)[t];
    else            g_y[t] = yw[t];
}

__global__ void k1_norm_x(const float* __restrict__ x) {
    int row = blockIdx.x;
    int t = threadIdx.x; // 128
    float4 v = ((const float4*)(x + row * DD))[t];
    float ss = v.x * v.x + v.y * v.y + v.z * v.z + v.w * v.w;
    #pragma unroll
    for (int o = 16; o; o >>= 1) ss += __shfl_xor_sync(0xffffffffu, ss, o);
    __shared__ float ws[4];
    if ((t & 31) == 0) ws[t >> 5] = ss;
    __syncthreads();
    float tot = ws[0] + ws[1] + ws[2] + ws[3];
    float sc = 1.0f / fmaxf(sqrtf(tot), 1e-12f);
    float4 o4 = make_float4(v.x * sc, v.y * sc, v.z * sc, v.w * sc);
    ((float4*)(g_xn + row * DD))[t] = o4;
    __nv_bfloat162 p0 = __floats2bfloat162_rn(o4.x, o4.y);
    __nv_bfloat162 p1 = __floats2bfloat162_rn(o4.z, o4.w);
    ((__nv_bfloat162*)(g_xnb + row * DD))[2 * t]     = p0;
    ((__nv_bfloat162*)(g_xnb + row * DD))[2 * t + 1] = p1;
}

// k1b: L2-normalize rows of W -> bf16. One warp per row, 8 rows per block.
__global__ __launch_bounds__(256) void k1b_norm_w(const float* __restrict__ Wm) {
    int wid = threadIdx.x >> 5, lane = threadIdx.x & 31;
    int row = blockIdx.x * 8 + wid;
    const float4* wr = (const float4*)(Wm + (size_t)row * DD);
    float4 v[4];
    float ss = 0.f;
    #pragma unroll
    for (int i = 0; i < 4; i++) {
        v[i] = wr[lane + i * 32];
        ss += v[i].x * v[i].x + v[i].y * v[i].y + v[i].z * v[i].z + v[i].w * v[i].w;
    }
    #pragma unroll
    for (int o = 16; o; o >>= 1) ss += __shfl_xor_sync(0xffffffffu, ss, o);
    float sc = 1.0f / fmaxf(sqrtf(ss), 1e-12f);
    __nv_bfloat162* out = (__nv_bfloat162*)(g_wnb + (size_t)row * DD);
    #pragma unroll
    for (int i = 0; i < 4; i++) {
        __nv_bfloat162 p0 = __floats2bfloat162_rn(v[i].x * sc, v[i].y * sc);
        __nv_bfloat162 p1 = __floats2bfloat162_rn(v[i].z * sc, v[i].w * sc);
        out[(lane + i * 32) * 2]     = p0;
        out[(lane + i * 32) * 2 + 1] = p1;
    }
}

// ---------------------------------------------------------------------------
// k2: HMMA GEMM, 256 threads / 8 warps (2x4, warp tile 64x32), 128Mx128N,
// BK=32, 4-stage cp.async, 2 CTAs/SM (launch_bounds). theta = acc directly.
// Epilogue: exp + target mask + row-sum -> g_partial.
// ---------------------------------------------------------------------------
__global__ __launch_bounds__(256, 2) void k2_gemm() {
    extern __shared__ char smem[];
    const uint32_t sb = (uint32_t)__cvta_generic_to_shared(smem);
    const int t = threadIdx.x, lane = t & 31, wp = t >> 5;
    const int wm = wp >> 2, wn = wp & 3;
    const int mt = blockIdx.x, nt = blockIdx.y;
    const int m0 = mt * BM, n0 = nt * BN;

    if (t < BM) ((int*)(smem + SY_OFF))[t] = g_y[m0 + t];

    auto fillA = [&](int ks, int buf) {
        #pragma unroll
        for (int i = 0; i < 2; i++) {
            int idx = i * 256 + t, r = idx >> 2, c = idx & 3;
            cpasync16(sb + A_OFF + buf * A_STG + (r * AROW + c * 8) * 2,
                      g_xnb + (m0 + r) * DD + ks * BK + c * 8);
        }
    };
    auto fillB = [&](int ks, int buf) {
        #pragma unroll
        for (int i = 0; i < 2; i++) {
            int idx = i * 256 + t, r = idx >> 2, c = idx & 3;
            cpasync16(sb + B_OFF + buf * B_STG + (r * AROW + c * 8) * 2,
                      g_wnb + (size_t)(n0 + r) * DD + ks * BK + c * 8);
        }
    };

    float acc[4][4][4];
    #pragma unroll
    for (int i = 0; i < 4; i++)
        #pragma unroll
        for (int j = 0; j < 4; j++)
            #pragma unroll
            for (int k = 0; k < 4; k++) acc[i][j][k] = 0.f;

    uint32_t aoff[4], boff[2];
    #pragma unroll
    for (int mf = 0; mf < 4; mf++)
        aoff[mf] = sb + A_OFF + ((wm * 64 + mf * 16 + (lane & 15)) * AROW + (lane >> 4) * 8) * 2;
    #pragma unroll
    for (int g = 0; g < 2; g++)
        boff[g] = sb + B_OFF + ((wn * 32 + g * 16 + (lane & 15)) * AROW + (lane >> 4) * 8) * 2;

    fillA(0, 0); fillB(0, 0); cpcommit();
    fillA(1, 1); fillB(1, 1); cpcommit();
    fillA(2, 2); fillB(2, 2); cpcommit();

    for (int ks = 0; ks < NSTG; ks++) {
        cpwait2();
        __syncthreads();
        int nx = ks + 3;
        if (nx < NSTG) { fillA(nx, nx & 3); fillB(nx, nx & 3); }
        cpcommit();

        const uint32_t abase = (uint32_t)((ks & 3) * A_STG);
        const uint32_t bbase = (uint32_t)((ks & 3) * B_STG);
        #pragma unroll
        for (int kc = 0; kc < 2; kc++) {
            uint32_t bfrag[2][4];
            ldsm4(bfrag[0], boff[0] + bbase + kc * 32);
            ldsm4(bfrag[1], boff[1] + bbase + kc * 32);
            #pragma unroll
            for (int mf = 0; mf < 4; mf++) {
                uint32_t afrag[4];
                ldsm4(afrag, aoff[mf] + abase + kc * 32);
                #pragma unroll
                for (int nf = 0; nf < 4; nf++) {
                    int g = nf >> 1, h = nf & 1;
                    mma16816(acc[mf][nf], afrag, bfrag[g][h], bfrag[g][2 + h]);
                }
            }
        }
        __syncthreads();
    }

    // epilogue: theta = acc (pre-normalized operands)
    const int* sy = (const int*)(smem + SY_OFF);
    float* rowacc = (float*)(smem + RA_OFF);
    #pragma unroll
    for (int mf = 0; mf < 4; mf++) {
        #pragma unroll
        for (int h = 0; h < 2; h++) {
            int row = wm * 64 + mf * 16 + h * 8 + (lane >> 2);
            int yrel = sy[row] - n0;
            float rsum = 0.f;
            #pragma unroll
            for (int nf = 0; nf < 4; nf++) {
                int nl = wn * 32 + nf * 8 + (lane & 3) * 2;
                float e0 = __expf(64.0f * acc[mf][nf][h * 2]);
                float e1 = __expf(64.0f * acc[mf][nf][h * 2 + 1]);
                rsum += (nl     == yrel) ? 0.f : e0;
                rsum += (nl + 1 == yrel) ? 0.f : e1;
            }
            rsum += __shfl_xor_sync(0xffffffffu, rsum, 1);
            rsum += __shfl_xor_sync(0xffffffffu, rsum, 2);
            if ((lane & 3) == 0) rowacc[row * 4 + wn] = rsum;
        }
    }
    __syncthreads();
    if (t < BM)
        g_partial[(mt * NT + nt) * BM + t] =
            (rowacc[t * 4] + rowacc[t * 4 + 1]) + (rowacc[t * 4 + 2] + rowacc[t * 4 + 3]);
}

// ---------------------------------------------------------------------------
// k3: per-row finalize, one block per row, 512 threads.
// ---------------------------------------------------------------------------
__global__ __launch_bounds__(512) void k3_final(const float* __restrict__ Wm) {
    __shared__ double sd[512];
    __shared__ float  sf[128], sg[128];
    int b = blockIdx.x, t = threadIdx.x;
    int yb = g_y[b];
    int mt = b >> 7, ml = b & 127;

    double ex = (t < NT) ? (double)g_partial[(mt * NT + t) * BM + ml] : 0.0;

    if (t < 128) {
        float4 wv = ((const float4*)(Wm + (size_t)yb * DD))[t];
        float4 xv = ((const float4*)(g_xn + b * DD))[t];
        sf[t] = wv.x * xv.x + wv.y * xv.y + wv.z * xv.z + wv.w * xv.w;
        sg[t] = wv.x * wv.x + wv.y * wv.y + wv.z * wv.z + wv.w * wv.w;
    }
    sd[t] = ex;
    __syncthreads();
    for (int s = 256; s >= 128; s >>= 1) {
        if (t < s) sd[t] += sd[t + s];
        __syncthreads();
    }
    for (int s = 64; s; s >>= 1) {
        if (t < s) { sd[t] += sd[t + s]; sf[t] += sf[t + s]; sg[t] += sg[t + s]; }
        __syncthreads();
    }
    if (t == 0) {
        double tgt = (double)sf[0] / fmax(sqrt((double)sg[0]), 1e-12);
        double tc = fmin(fmax(tgt, -1.0 + 1e-7), 1.0 - 1e-7);
        double num = 64.0 * cos(acos(tc) + 0.5);
        double den = exp(num) + sd[0];
        g_term[b] = num - log(den);
    }
}

__global__ void k4_reduce(float* __restrict__ out) {
    __shared__ double sm[BB];
    int t = threadIdx.x;
    sm[t] = g_term[t];
    __syncthreads();
    for (int s = BB / 2; s; s >>= 1) {
        if (t < s) sm[t] += sm[t + s];
        __syncthreads();
    }
    if (t == 0) out[0] = (float)(-sm[0] / (double)BB);
}

extern "C" void kernel_launch(void* const* d_in, const int* in_sizes, int n_in,
                              void* d_out, int out_size) {
    const float* x = (const float*)d_in[0];
    const int*   y = (const int*)d_in[1];
    const float* W = (const float*)d_in[2];

    cudaFuncSetAttribute(k2_gemm, cudaFuncAttributeMaxDynamicSharedMemorySize, SMEM_TOTAL);

    k0_decode_y<<<1, BB>>>(y);
    k1_norm_x<<<BB, 128>>>(x);
    k1b_norm_w<<<CC / 8, 256>>>(W);
    k2_gemm<<<dim3(MT, NT), 256, SMEM_TOTAL>>>();
    k3_final<<<BB, 512>>>(W);
    k4_reduce<<<1, BB>>>((float*)d_out);
}

// round 7
// speedup vs baseline: 1.0477x; 1.0477x over previous
#include <cuda_runtime.h>
#include <cuda_bf16.h>
#include <cstdint>

// ArcFace loss, fused. HMMA GEMM (tcgen05 unavailable: harness targets compute_103 base).
// B=512, D=512, C=64000.
constexpr int BB = 512;
constexpr int DD = 512;
constexpr int CC = 64000;

constexpr int BM = 128, BN = 128, BK = 32;
constexpr int MT = BB / BM;    // 4
constexpr int NT = CC / BN;    // 500
constexpr int NSTG = DD / BK;  // 16
constexpr int AROW = 40;       // smem row stride (halfs); ldsm conflict-free
constexpr int STG  = BM * AROW * 2;   // 10240 B (A and B stages equal)
constexpr int NPIPE = 5;

// dynamic smem layout
constexpr int A_OFF  = 0;                      // 5 stages
constexpr int B_OFF  = NPIPE * STG;            // 51200, 5 stages
constexpr int SY_OFF = B_OFF + NPIPE * STG;    // 102400: 128 ints
constexpr int RA_OFF = SY_OFF + 512;           // 102912: 128x4 floats
constexpr int SMEM_TOTAL = RA_OFF + 2048;      // 104960 (x2 CTA = 210KB <= 228KB)

__device__ float         g_xn[BB * DD];    // normalized x fp32 (k3 exact dot)
__device__ __nv_bfloat16 g_xnb[BB * DD];   // normalized x bf16 (GEMM A)
__device__ __nv_bfloat16 g_wnb[CC * DD];   // normalized W bf16 (GEMM B)
__device__ int           g_y[BB];
__device__ float         g_partial[MT * NT * BM];
__device__ double        g_term[BB];

// ---------------- PTX helpers ----------------
__device__ __forceinline__ void ldsm4(uint32_t* r, uint32_t a) {
    asm volatile("ldmatrix.sync.aligned.m8n8.x4.shared.b16 {%0,%1,%2,%3}, [%4];"
        : "=r"(r[0]), "=r"(r[1]), "=r"(r[2]), "=r"(r[3]) : "r"(a));
}
__device__ __forceinline__ void mma16816(float* c, const uint32_t* a, uint32_t b0, uint32_t b1) {
    asm volatile("mma.sync.aligned.m16n8k16.row.col.f32.bf16.bf16.f32 "
        "{%0,%1,%2,%3}, {%4,%5,%6,%7}, {%8,%9}, {%0,%1,%2,%3};"
        : "+f"(c[0]), "+f"(c[1]), "+f"(c[2]), "+f"(c[3])
        : "r"(a[0]), "r"(a[1]), "r"(a[2]), "r"(a[3]), "r"(b0), "r"(b1));
}
__device__ __forceinline__ void cpasync16(uint32_t smem, const void* gptr) {
    asm volatile("cp.async.cg.shared.global [%0], [%1], 16;"
        :: "r"(smem), "l"(gptr) : "memory");
}
__device__ __forceinline__ void cpcommit() { asm volatile("cp.async.commit_group;" ::: "memory"); }
__device__ __forceinline__ void cpwait3() { asm volatile("cp.async.wait_group 3;" ::: "memory"); }

// ---------------------------------------------------------------------------
__global__ void k0_decode_y(const int* __restrict__ yw) {
    __shared__ int oddnz;
    int t = threadIdx.x;
    if (t == 0) oddnz = 0;
    __syncthreads();
    if (t < 256 && yw[2 * t + 1] != 0) atomicOr(&oddnz, 1);
    __syncthreads();
    if (oddnz == 0) g_y[t] = (int)((const long long*)yw)[t];
    else            g_y[t] = yw[t];
}

__global__ void k1_norm_x(const float* __restrict__ x) {
    int row = blockIdx.x;
    int t = threadIdx.x; // 128
    float4 v = ((const float4*)(x + row * DD))[t];
    float ss = v.x * v.x + v.y * v.y + v.z * v.z + v.w * v.w;
    #pragma unroll
    for (int o = 16; o; o >>= 1) ss += __shfl_xor_sync(0xffffffffu, ss, o);
    __shared__ float ws[4];
    if ((t & 31) == 0) ws[t >> 5] = ss;
    __syncthreads();
    float tot = ws[0] + ws[1] + ws[2] + ws[3];
    float sc = 1.0f / fmaxf(sqrtf(tot), 1e-12f);
    float4 o4 = make_float4(v.x * sc, v.y * sc, v.z * sc, v.w * sc);
    ((float4*)(g_xn + row * DD))[t] = o4;
    __nv_bfloat162 p0 = __floats2bfloat162_rn(o4.x, o4.y);
    __nv_bfloat162 p1 = __floats2bfloat162_rn(o4.z, o4.w);
    ((__nv_bfloat162*)(g_xnb + row * DD))[2 * t]     = p0;
    ((__nv_bfloat162*)(g_xnb + row * DD))[2 * t + 1] = p1;
}

// k1b: L2-normalize rows of W -> bf16. One warp per row, 8 rows per block.
__global__ __launch_bounds__(256) void k1b_norm_w(const float* __restrict__ Wm) {
    int wid = threadIdx.x >> 5, lane = threadIdx.x & 31;
    int row = blockIdx.x * 8 + wid;
    const float4* wr = (const float4*)(Wm + (size_t)row * DD);
    float4 v[4];
    float ss = 0.f;
    #pragma unroll
    for (int i = 0; i < 4; i++) {
        v[i] = wr[lane + i * 32];
        ss += v[i].x * v[i].x + v[i].y * v[i].y + v[i].z * v[i].z + v[i].w * v[i].w;
    }
    #pragma unroll
    for (int o = 16; o; o >>= 1) ss += __shfl_xor_sync(0xffffffffu, ss, o);
    float sc = 1.0f / fmaxf(sqrtf(ss), 1e-12f);
    __nv_bfloat162* out = (__nv_bfloat162*)(g_wnb + (size_t)row * DD);
    #pragma unroll
    for (int i = 0; i < 4; i++) {
        __nv_bfloat162 p0 = __floats2bfloat162_rn(v[i].x * sc, v[i].y * sc);
        __nv_bfloat162 p1 = __floats2bfloat162_rn(v[i].z * sc, v[i].w * sc);
        out[(lane + i * 32) * 2]     = p0;
        out[(lane + i * 32) * 2 + 1] = p1;
    }
}

// ---------------------------------------------------------------------------
// k2: HMMA GEMM, 256 threads / 8 warps (2x4, warp tile 64x32), 128Mx128N,
// BK=32, 5-stage cp.async (single sync/stage), 2 CTAs/SM. All addressing
// hoisted to registers; rotating buffer offsets (no modulo in loop).
// ---------------------------------------------------------------------------
__global__ __launch_bounds__(256, 2) void k2_gemm() {
    extern __shared__ char smem[];
    const uint32_t sb = (uint32_t)__cvta_generic_to_shared(smem);
    const int t = threadIdx.x, lane = t & 31, wp = t >> 5;
    const int wm = wp >> 2, wn = wp & 3;
    const int mt = blockIdx.x, nt = blockIdx.y;
    const int m0 = mt * BM, n0 = nt * BN;

    if (t < BM) ((int*)(smem + SY_OFF))[t] = g_y[m0 + t];

    // hoisted producer addressing: rows t>>2 and 64+(t>>2), col chunk (t&3)*8
    const int pr = t >> 2, pc = (t & 3) * 8;
    const __nv_bfloat16* gA0 = g_xnb + (m0 + pr) * DD + pc;
    const __nv_bfloat16* gA1 = gA0 + 64 * DD;
    const __nv_bfloat16* gB0 = g_wnb + (size_t)(n0 + pr) * DD + pc;
    const __nv_bfloat16* gB1 = gB0 + 64 * DD;
    const uint32_t sA0 = sb + A_OFF + (pr * AROW + pc) * 2;
    const uint32_t sA1 = sA0 + 64 * AROW * 2;
    const uint32_t sB0 = sb + B_OFF + (pr * AROW + pc) * 2;
    const uint32_t sB1 = sB0 + 64 * AROW * 2;
    uint32_t wo = 0;  // write buffer offset (rotates 0..4*STG)

    auto fill = [&]() {
        cpasync16(sA0 + wo, gA0);
        cpasync16(sA1 + wo, gA1);
        cpasync16(sB0 + wo, gB0);
        cpasync16(sB1 + wo, gB1);
        gA0 += BK; gA1 += BK; gB0 += BK; gB1 += BK;
        wo += STG; if (wo == NPIPE * STG) wo = 0;
    };

    float acc[4][4][4];
    #pragma unroll
    for (int i = 0; i < 4; i++)
        #pragma unroll
        for (int j = 0; j < 4; j++)
            #pragma unroll
            for (int k = 0; k < 4; k++) acc[i][j][k] = 0.f;

    uint32_t aoff[4], boff[2];
    #pragma unroll
    for (int mf = 0; mf < 4; mf++)
        aoff[mf] = sb + A_OFF + ((wm * 64 + mf * 16 + (lane & 15)) * AROW + (lane >> 4) * 8) * 2;
    #pragma unroll
    for (int g = 0; g < 2; g++)
        boff[g] = sb + B_OFF + ((wn * 32 + g * 16 + (lane & 15)) * AROW + (lane >> 4) * 8) * 2;

    fill(); cpcommit();
    fill(); cpcommit();
    fill(); cpcommit();
    fill(); cpcommit();

    uint32_t ro = 0;  // read buffer offset
    for (int ks = 0; ks < NSTG; ks++) {
        cpwait3();
        __syncthreads();
        if (ks + 4 < NSTG) fill();
        cpcommit();

        #pragma unroll
        for (int kc = 0; kc < 2; kc++) {
            uint32_t bfrag[2][4];
            ldsm4(bfrag[0], boff[0] + ro + kc * 32);
            ldsm4(bfrag[1], boff[1] + ro + kc * 32);
            #pragma unroll
            for (int mf = 0; mf < 4; mf++) {
                uint32_t afrag[4];
                ldsm4(afrag, aoff[mf] + ro + kc * 32);
                #pragma unroll
                for (int nf = 0; nf < 4; nf++) {
                    int g = nf >> 1, h = nf & 1;
                    mma16816(acc[mf][nf], afrag, bfrag[g][h], bfrag[g][2 + h]);
                }
            }
        }
        ro += STG; if (ro == NPIPE * STG) ro = 0;
    }
    __syncthreads();

    // epilogue: theta = acc (pre-normalized operands)
    const int* sy = (const int*)(smem + SY_OFF);
    float* rowacc = (float*)(smem + RA_OFF);
    #pragma unroll
    for (int mf = 0; mf < 4; mf++) {
        #pragma unroll
        for (int h = 0; h < 2; h++) {
            int row = wm * 64 + mf * 16 + h * 8 + (lane >> 2);
            int yrel = sy[row] - n0;
            float rsum = 0.f;
            #pragma unroll
            for (int nf = 0; nf < 4; nf++) {
                int nl = wn * 32 + nf * 8 + (lane & 3) * 2;
                float e0 = __expf(64.0f * acc[mf][nf][h * 2]);
                float e1 = __expf(64.0f * acc[mf][nf][h * 2 + 1]);
                rsum += (nl     == yrel) ? 0.f : e0;
                rsum += (nl + 1 == yrel) ? 0.f : e1;
            }
            rsum += __shfl_xor_sync(0xffffffffu, rsum, 1);
            rsum += __shfl_xor_sync(0xffffffffu, rsum, 2);
            if ((lane & 3) == 0) rowacc[row * 4 + wn] = rsum;
        }
    }
    __syncthreads();
    if (t < BM)
        g_partial[(mt * NT + nt) * BM + t] =
            (rowacc[t * 4] + rowacc[t * 4 + 1]) + (rowacc[t * 4 + 2] + rowacc[t * 4 + 3]);
}

// ---------------------------------------------------------------------------
// k3: per-row finalize, one block per row, 512 threads.
// ---------------------------------------------------------------------------
__global__ __launch_bounds__(512) void k3_final(const float* __restrict__ Wm) {
    __shared__ double sd[512];
    __shared__ float  sf[128], sg[128];
    int b = blockIdx.x, t = threadIdx.x;
    int yb = g_y[b];
    int mt = b >> 7, ml = b & 127;

    double ex = (t < NT) ? (double)g_partial[(mt * NT + t) * BM + ml] : 0.0;

    if (t < 128) {
        float4 wv = ((const float4*)(Wm + (size_t)yb * DD))[t];
        float4 xv = ((const float4*)(g_xn + b * DD))[t];
        sf[t] = wv.x * xv.x + wv.y * xv.y + wv.z * xv.z + wv.w * xv.w;
        sg[t] = wv.x * wv.x + wv.y * wv.y + wv.z * wv.z + wv.w * wv.w;
    }
    sd[t] = ex;
    __syncthreads();
    for (int s = 256; s >= 128; s >>= 1) {
        if (t < s) sd[t] += sd[t + s];
        __syncthreads();
    }
    for (int s = 64; s; s >>= 1) {
        if (t < s) { sd[t] += sd[t + s]; sf[t] += sf[t + s]; sg[t] += sg[t + s]; }
        __syncthreads();
    }
    if (t == 0) {
        double tgt = (double)sf[0] / fmax(sqrt((double)sg[0]), 1e-12);
        double tc = fmin(fmax(tgt, -1.0 + 1e-7), 1.0 - 1e-7);
        double num = 64.0 * cos(acos(tc) + 0.5);
        double den = exp(num) + sd[0];
        g_term[b] = num - log(den);
    }
}

__global__ void k4_reduce(float* __restrict__ out) {
    __shared__ double sm[BB];
    int t = threadIdx.x;
    sm[t] = g_term[t];
    __syncthreads();
    for (int s = BB / 2; s; s >>= 1) {
        if (t < s) sm[t] += sm[t + s];
        __syncthreads();
    }
    if (t == 0) out[0] = (float)(-sm[0] / (double)BB);
}

extern "C" void kernel_launch(void* const* d_in, const int* in_sizes, int n_in,
                              void* d_out, int out_size) {
    const float* x = (const float*)d_in[0];
    const int*   y = (const int*)d_in[1];
    const float* W = (const float*)d_in[2];

    cudaFuncSetAttribute(k2_gemm, cudaFuncAttributeMaxDynamicSharedMemorySize, SMEM_TOTAL);

    k0_decode_y<<<1, BB>>>(y);
    k1_norm_x<<<BB, 128>>>(x);
    k1b_norm_w<<<CC / 8, 256>>>(W);
    k2_gemm<<<dim3(MT, NT), 256, SMEM_TOTAL>>>();
    k3_final<<<BB, 512>>>(W);
    k4_reduce<<<1, BB>>>((float*)d_out);
}